// round 1
// baseline (speedup 1.0000x reference)
#include <cuda_runtime.h>

#define TT 200
#define BB 1024
#define DD 128
#define NN 384   // 3 gates * 128

// ---------------- device scratch (no runtime allocation allowed) ----------------
__device__ float g_Wa[DD * NN];                       // packed [k][n] n = gate*128+d
__device__ float g_Wb[DD * NN];
__device__ float g_bias[NN];
__device__ float g_Ax[(size_t)TT * BB * NN];          // precomputed x-projections (+bias)

// ---------------- f32x2 packed-FMA helpers (Blackwell dual-fp32) ----------------
static __device__ __forceinline__ unsigned long long pk2(float lo, float hi) {
    unsigned long long r;
    asm("mov.b64 %0, {%1,%2};" : "=l"(r) : "f"(lo), "f"(hi));
    return r;
}
static __device__ __forceinline__ void upk2(unsigned long long v, float &lo, float &hi) {
    asm("mov.b64 {%0,%1}, %2;" : "=f"(lo), "=f"(hi) : "l"(v));
}
static __device__ __forceinline__ unsigned long long ffma2(unsigned long long a,
                                                           unsigned long long b,
                                                           unsigned long long c) {
    unsigned long long d;
    asm("fma.rn.f32x2 %0, %1, %2, %3;" : "=l"(d) : "l"(a), "l"(b), "l"(c));
    return d;
}

static __device__ __forceinline__ float fsig(float x) {
    // 1 / (1 + e^-x); __expf overflow to +inf gives 1/inf = 0 -> correct limit
    return __fdividef(1.f, 1.f + __expf(-x));
}
static __device__ __forceinline__ float ftanh(float x) {
    float y = fminf(fmaxf(2.f * x, -30.f), 30.f);
    float e = __expf(y);
    return __fdividef(e - 1.f, e + 1.f);
}

// ---------------- pack weights into [k][gate*128+d] layout ----------------
__global__ void pack_kernel(const float* __restrict__ Wau, const float* __restrict__ bau,
                            const float* __restrict__ Wbu, const float* __restrict__ War,
                            const float* __restrict__ bar, const float* __restrict__ Wbr,
                            const float* __restrict__ Wac, const float* __restrict__ bac,
                            const float* __restrict__ Wbc) {
    int idx = blockIdx.x * blockDim.x + threadIdx.x;
    if (idx < DD * NN) {
        int k = idx / NN;
        int n = idx - k * NN;
        int g = n >> 7;
        int d = n & 127;
        const float* A = (g == 0) ? Wau : ((g == 1) ? War : Wac);
        const float* Bm = (g == 0) ? Wbu : ((g == 1) ? Wbr : Wbc);
        g_Wa[idx] = A[k * DD + d];
        g_Wb[idx] = Bm[k * DD + d];
    }
    if (idx < NN) {
        int g = idx >> 7;
        int d = idx & 127;
        const float* bb = (g == 0) ? bau : ((g == 1) ? bar : bac);
        g_bias[idx] = bb[d];
    }
}

// ---------------- phase 1: Ax = X @ [Wau|War|Wac] + bias ----------------
// Persistent: each of 148 CTAs loops over 8-row chunks. Thread n holds
// weight column n (128 fp32) in registers; X rows broadcast from smem.
__global__ __launch_bounds__(384, 1)
void xproj_kernel(const float* __restrict__ X) {
    __shared__ __align__(16) float x_sh[2][DD][8];   // [buf][k][row]
    const int tid = threadIdx.x;

    float w[DD];
#pragma unroll
    for (int k = 0; k < DD; k++) w[k] = g_Wa[k * NN + tid];
    const float bias = g_bias[tid];

    const int NCHUNK = TT * BB / 8;   // 25600

    // prefetch chunk 0 into buf 0
    int c = blockIdx.x;
    {
        const float* p = X + (size_t)c * (8 * DD);
        float v0 = p[tid];
        float v1 = p[tid + 384];
        float v2 = (tid < 256) ? p[tid + 768] : 0.f;
        int i0 = tid, i1 = tid + 384;
        x_sh[0][i0 & 127][i0 >> 7] = v0;
        x_sh[0][i1 & 127][i1 >> 7] = v1;
        if (tid < 256) { int i2 = tid + 768; x_sh[0][i2 & 127][i2 >> 7] = v2; }
    }
    __syncthreads();

    int buf = 0;
    for (; c < NCHUNK; c += gridDim.x) {
        const int cn = c + gridDim.x;
        float v0 = 0.f, v1 = 0.f, v2 = 0.f;
        if (cn < NCHUNK) {
            const float* p = X + (size_t)cn * (8 * DD);
            v0 = p[tid];
            v1 = p[tid + 384];
            v2 = (tid < 256) ? p[tid + 768] : 0.f;
        }

        unsigned long long acc0 = 0ull, acc1 = 0ull, acc2 = 0ull, acc3 = 0ull;
#pragma unroll
        for (int k = 0; k < DD; k++) {
            unsigned long long w2 = pk2(w[k], w[k]);
            ulonglong2 sA = *(const ulonglong2*)&x_sh[buf][k][0];
            ulonglong2 sB = *(const ulonglong2*)&x_sh[buf][k][4];
            acc0 = ffma2(sA.x, w2, acc0);
            acc1 = ffma2(sA.y, w2, acc1);
            acc2 = ffma2(sB.x, w2, acc2);
            acc3 = ffma2(sB.y, w2, acc3);
        }
        float a[8];
        upk2(acc0, a[0], a[1]);
        upk2(acc1, a[2], a[3]);
        upk2(acc2, a[4], a[5]);
        upk2(acc3, a[6], a[7]);

        float* outp = g_Ax + (size_t)c * 8 * NN + tid;
#pragma unroll
        for (int r = 0; r < 8; r++) outp[(size_t)r * NN] = a[r] + bias;

        // stage next chunk into the other buffer (safe: its last readers
        // finished at the previous iteration's barrier)
        if (cn < NCHUNK) {
            int i0 = tid, i1 = tid + 384;
            x_sh[buf ^ 1][i0 & 127][i0 >> 7] = v0;
            x_sh[buf ^ 1][i1 & 127][i1 >> 7] = v1;
            if (tid < 256) { int i2 = tid + 768; x_sh[buf ^ 1][i2 & 127][i2 >> 7] = v2; }
        }
        __syncthreads();
        buf ^= 1;
    }
}

// ---------------- phase 2: recurrence, 1 CTA = 8 independent batch rows ----------------
// Thread n in [0,384): gate = n/128, d = n%128. Holds Wb column n in registers.
__global__ __launch_bounds__(384, 1)
void recur_kernel(const float* __restrict__ state0,
                  const float* __restrict__ att,    // [T,B,1]
                  const float* __restrict__ mask,   // [B,T]
                  float* __restrict__ out) {
    __shared__ __align__(16) float s_sh[DD][8];
    __shared__ float r_sh[DD][8];
    __shared__ float u_sh[DD][8];
    __shared__ float am_sh[2][8];   // [0]=att, [1]=mask for this step

    const int tid = threadIdx.x;
    const int b0 = blockIdx.x * 8;
    const int gate = tid >> 7;
    const int d = tid & 127;

    float w[DD];
#pragma unroll
    for (int k = 0; k < DD; k++) w[k] = g_Wb[k * NN + tid];

    for (int idx = tid; idx < 8 * DD; idx += 384) {
        int j = idx >> 7, dd = idx & 127;
        s_sh[dd][j] = state0[(b0 + j) * DD + dd];
    }
    __syncthreads();

    for (int t = 0; t < TT; t++) {
        // prefetch this step's x-projection rows + att/mask (hidden under matvec)
        const float* axp = g_Ax + ((size_t)t * BB + b0) * NN + tid;
        float ax[8];
#pragma unroll
        for (int j = 0; j < 8; j++) ax[j] = axp[(size_t)j * NN];
        if (tid < 8) {
            am_sh[0][tid] = att[t * BB + b0 + tid];
            am_sh[1][tid] = mask[(b0 + tid) * TT + t];
        }

        // acc[n][b] = sum_k s[k][b] * Wb[k][n]
        unsigned long long acc0 = 0ull, acc1 = 0ull, acc2 = 0ull, acc3 = 0ull;
#pragma unroll
        for (int k = 0; k < DD; k++) {
            unsigned long long w2 = pk2(w[k], w[k]);
            ulonglong2 sA = *(const ulonglong2*)&s_sh[k][0];
            ulonglong2 sB = *(const ulonglong2*)&s_sh[k][4];
            acc0 = ffma2(sA.x, w2, acc0);
            acc1 = ffma2(sA.y, w2, acc1);
            acc2 = ffma2(sB.x, w2, acc2);
            acc3 = ffma2(sB.y, w2, acc3);
        }
        float acc[8];
        upk2(acc0, acc[0], acc[1]);
        upk2(acc1, acc[2], acc[3]);
        upk2(acc2, acc[4], acc[5]);
        upk2(acc3, acc[6], acc[7]);

        if (gate == 0) {          // u pre-activation -> sigmoid
#pragma unroll
            for (int j = 0; j < 8; j++) u_sh[d][j] = fsig(ax[j] + acc[j]);
        } else if (gate == 1) {   // r pre-activation -> sigmoid
#pragma unroll
            for (int j = 0; j < 8; j++) r_sh[d][j] = fsig(ax[j] + acc[j]);
        }
        __syncthreads();          // u,r,att,mask visible; matvec reads of s_sh done

        if (gate == 2) {          // candidate + state update (owns row d)
#pragma unroll
            for (int j = 0; j < 8; j++) {
                float cval = ftanh(ax[j] + r_sh[d][j] * acc[j]);
                float ustar = am_sh[0][j] * u_sh[d][j];
                float so = s_sh[d][j];
                // s_new = m*((1-u)*s + u*c) + (1-m)*s  ==  s + m*u*(c-s)
                s_sh[d][j] = so + am_sh[1][j] * (ustar * (cval - so));
            }
        }
        __syncthreads();          // s_sh update visible before next matvec
    }

    for (int idx = tid; idx < 8 * DD; idx += 384) {
        int j = idx >> 7, dd = idx & 127;
        out[(b0 + j) * DD + dd] = s_sh[dd][j];
    }
}

// ---------------- launch ----------------
extern "C" void kernel_launch(void* const* d_in, const int* in_sizes, int n_in,
                              void* d_out, int out_size) {
    const float* inputs = (const float*)d_in[0];   // [T,B,D]
    const float* state  = (const float*)d_in[1];   // [B,D]
    const float* att    = (const float*)d_in[2];   // [T,B,1]
    const float* mask   = (const float*)d_in[3];   // [B,T]
    // d_in[4] = max_len (compile-time constant TT, ignored)
    const float* Wau = (const float*)d_in[5];
    const float* bau = (const float*)d_in[6];
    const float* Wbu = (const float*)d_in[7];
    const float* War = (const float*)d_in[8];
    const float* bar = (const float*)d_in[9];
    const float* Wbr = (const float*)d_in[10];
    const float* Wac = (const float*)d_in[11];
    const float* bac = (const float*)d_in[12];
    const float* Wbc = (const float*)d_in[13];

    pack_kernel<<<(DD * NN + 255) / 256, 256>>>(Wau, bau, Wbu, War, bar, Wbr, Wac, bac, Wbc);
    xproj_kernel<<<148, 384>>>(inputs);
    recur_kernel<<<BB / 8, 384>>>(state, att, mask, (float*)d_out);
}